// round 5
// baseline (speedup 1.0000x reference)
#include <cuda_runtime.h>

// ---------------------------------------------------------------------------
// signalEncoding: B=256, S=512, SF=4, NSIG=50
// Kernel A (prep): x -> sharedCNN(sharedCNN(x)) + x -> LayerNorm -> scratch d
// Kernel B (sig):  per-signal 4-layer conv stack on d -> out (B,50,512)
// Batch packed 2-wide into f32x2 (fma.rn.f32x2). All intermediates in SMEM.
// ---------------------------------------------------------------------------

#define NPOS 512
#define HALO 4
#define CST  528           // per-channel smem stride (float2 elems), 528 % 16 == 0
#define NBP  128           // batch pairs

// swizzled smem index: XOR of low 2 bits with bits[5:4] — bijective, and
// conflict-free for the lane-stride-4 float2 pattern q = 4*lane + K (any K).
__device__ __forceinline__ int sidx(int c, int p) {
    int q = p + HALO;                    // q in [0, 519]
    return c * CST + (q ^ ((q >> 4) & 3));
}

union F2U { float2 f; unsigned long long u; };

__device__ __forceinline__ float2 ffma2(float2 a, float2 b, float2 c) {
    F2U ua, ub, uc, ud;
    ua.f = a; ub.f = b; uc.f = c;
    asm("fma.rn.f32x2 %0, %1, %2, %3;" : "=l"(ud.u) : "l"(ua.u), "l"(ub.u), "l"(uc.u));
    return ud.f;
}

__device__ __forceinline__ float2 add2(float2 a, float2 b) {
    return make_float2(a.x + b.x, a.y + b.y);
}

__device__ __forceinline__ float selu_s(float x) {
    const float SC = 1.0507009873554805f;      // lambda
    const float SA = 1.7580993408473766f;      // lambda * alpha
    return x > 0.f ? SC * x : SA * expm1f(x);
}
__device__ __forceinline__ float2 selu2(float2 v) {
    return make_float2(selu_s(v.x), selu_s(v.y));
}

// reflect halo: buf[-i] = buf[i], buf[511+i] = buf[511-i], i=1..4
__device__ __forceinline__ void fill_halo(float2* buf, int C, int tid) {
    if (tid < C * 8) {
        int c = tid >> 3, k = tid & 7;
        if (k < 4) { int i = k + 1; buf[sidx(c, -i)]      = buf[sidx(c, i)]; }
        else       { int i = k - 3; buf[sidx(c, 511 + i)] = buf[sidx(c, 511 - i)]; }
    }
}

// scratch: normalized d, float2 over batch pair: [(bp*4 + c)*512 + p]
__device__ float2 g_D[NBP * 4 * NPOS];

// ---------------------------------------------------------------------------
// Kernel A: prep.  grid=128 (batch pair), block=512 (one position per thread)
// ---------------------------------------------------------------------------

__device__ __forceinline__ void shared_conv1(const float2* S, float2* Dst,
                                             const float* w1, const float* b1, int t) {
    // 4 -> 8, k5, d1, pad2, SELU
    #pragma unroll
    for (int o = 0; o < 8; o++) {
        float2 acc = make_float2(b1[o], b1[o]);
        #pragma unroll
        for (int c = 0; c < 4; c++)
            #pragma unroll
            for (int j = 0; j < 5; j++) {
                float w = w1[o * 20 + c * 5 + j];
                acc = ffma2(make_float2(w, w), S[sidx(c, t - 2 + j)], acc);
            }
        Dst[sidx(o, t)] = selu2(acc);
    }
}

__device__ __forceinline__ void shared_conv2(const float2* S, const float* w2,
                                             const float* b2, int t, float2 out[4]) {
    // 8 -> 4, k5, d2, pad4 (no activation)
    #pragma unroll
    for (int o = 0; o < 4; o++) {
        float2 acc = make_float2(b2[o], b2[o]);
        #pragma unroll
        for (int c = 0; c < 8; c++)
            #pragma unroll
            for (int j = 0; j < 5; j++) {
                float w = w2[o * 40 + c * 5 + j];
                acc = ffma2(make_float2(w, w), S[sidx(c, t - 4 + 2 * j)], acc);
            }
        out[o] = acc;
    }
}

extern "C" __global__ void __launch_bounds__(512)
prep_kernel(const float* __restrict__ lat,
            const float* __restrict__ sw1, const float* __restrict__ sb1,
            const float* __restrict__ sw2, const float* __restrict__ sb2,
            const float* __restrict__ lng, const float* __restrict__ lnb) {
    extern __shared__ unsigned char sm[];
    float2* X   = (float2*)sm;            // 4 * CST
    float2* A   = X + 4 * CST;            // 8 * CST
    float2* Bu  = A + 8 * CST;            // 4 * CST
    float*  W   = (float*)(Bu + 4 * CST); // 336 floats
    float2* RED = (float2*)(W + 336);     // 64 float2

    const int t  = threadIdx.x;
    const int bp = blockIdx.x;
    const int lane = t & 31, wid = t >> 5;

    // stage weights: w1(160) b1(8) w2(160) b2(4)
    if (t < 332) {
        float v;
        if      (t < 160) v = sw1[t];
        else if (t < 168) v = sb1[t - 160];
        else if (t < 328) v = sw2[t - 168];
        else              v = sb2[t - 328];
        W[t] = v;
    }
    const float* w1 = W, * b1 = W + 160, * w2 = W + 168, * b2 = W + 328;

    // load latent: x[c][s] = latent[b][s*4+c], batch pair packed in float2
    float4 v0 = reinterpret_cast<const float4*>(lat + (size_t)(2 * bp)     * 2048)[t];
    float4 v1 = reinterpret_cast<const float4*>(lat + (size_t)(2 * bp + 1) * 2048)[t];
    X[sidx(0, t)] = make_float2(v0.x, v1.x);
    X[sidx(1, t)] = make_float2(v0.y, v1.y);
    X[sidx(2, t)] = make_float2(v0.z, v1.z);
    X[sidx(3, t)] = make_float2(v0.w, v1.w);
    __syncthreads();
    fill_halo(X, 4, t);
    __syncthreads();

    // pass 1: X -> Bu
    shared_conv1(X, A, w1, b1, t);
    __syncthreads(); fill_halo(A, 8, t); __syncthreads();
    {
        float2 tmp[4];
        shared_conv2(A, w2, b2, t, tmp);
        __syncthreads();                 // A reads done before overwriting later
        #pragma unroll
        for (int c = 0; c < 4; c++) Bu[sidx(c, t)] = tmp[c];
    }
    __syncthreads(); fill_halo(Bu, 4, t); __syncthreads();

    // pass 2: Bu -> dv (+ residual X)
    shared_conv1(Bu, A, w1, b1, t);
    __syncthreads(); fill_halo(A, 8, t); __syncthreads();
    float2 dv[4];
    {
        float2 cc[4];
        shared_conv2(A, w2, b2, t, cc);
        #pragma unroll
        for (int c = 0; c < 4; c++) dv[c] = add2(cc[c], X[sidx(c, t)]);
    }

    // -------- LayerNorm over positions (per channel, per batch), two-pass ----
    float2 mean[4], var[4];
    // pass A: mean
    {
        float2 sv[4];
        #pragma unroll
        for (int c = 0; c < 4; c++) sv[c] = dv[c];
        #pragma unroll
        for (int c = 0; c < 4; c++)
            for (int off = 16; off; off >>= 1) {
                sv[c].x += __shfl_xor_sync(0xffffffffu, sv[c].x, off);
                sv[c].y += __shfl_xor_sync(0xffffffffu, sv[c].y, off);
            }
        if (lane == 0)
            #pragma unroll
            for (int c = 0; c < 4; c++) RED[c * 16 + wid] = sv[c];
        __syncthreads();
        if (t < 32) {
            #pragma unroll
            for (int c = 0; c < 4; c++) {
                float2 v = (lane < 16) ? RED[c * 16 + lane] : make_float2(0.f, 0.f);
                for (int off = 8; off; off >>= 1) {
                    v.x += __shfl_xor_sync(0xffffffffu, v.x, off);
                    v.y += __shfl_xor_sync(0xffffffffu, v.y, off);
                }
                if (lane == 0) RED[c * 16] = v;
            }
        }
        __syncthreads();
        const float inv = 1.0f / 512.0f;
        #pragma unroll
        for (int c = 0; c < 4; c++) {
            float2 s = RED[c * 16];
            mean[c] = make_float2(s.x * inv, s.y * inv);
        }
        __syncthreads();   // before RED is reused
    }
    // pass B: variance
    {
        float2 sv[4];
        #pragma unroll
        for (int c = 0; c < 4; c++) {
            float dx = dv[c].x - mean[c].x, dy = dv[c].y - mean[c].y;
            sv[c] = make_float2(dx * dx, dy * dy);
        }
        #pragma unroll
        for (int c = 0; c < 4; c++)
            for (int off = 16; off; off >>= 1) {
                sv[c].x += __shfl_xor_sync(0xffffffffu, sv[c].x, off);
                sv[c].y += __shfl_xor_sync(0xffffffffu, sv[c].y, off);
            }
        if (lane == 0)
            #pragma unroll
            for (int c = 0; c < 4; c++) RED[c * 16 + wid] = sv[c];
        __syncthreads();
        if (t < 32) {
            #pragma unroll
            for (int c = 0; c < 4; c++) {
                float2 v = (lane < 16) ? RED[c * 16 + lane] : make_float2(0.f, 0.f);
                for (int off = 8; off; off >>= 1) {
                    v.x += __shfl_xor_sync(0xffffffffu, v.x, off);
                    v.y += __shfl_xor_sync(0xffffffffu, v.y, off);
                }
                if (lane == 0) RED[c * 16] = v;
            }
        }
        __syncthreads();
        const float inv = 1.0f / 512.0f;
        #pragma unroll
        for (int c = 0; c < 4; c++) {
            float2 s = RED[c * 16];
            var[c] = make_float2(s.x * inv, s.y * inv);
        }
    }

    const float EPS = 1e-10f;
    float g = lng[t], bb = lnb[t];
    #pragma unroll
    for (int c = 0; c < 4; c++) {
        float rx = 1.0f / sqrtf(var[c].x + EPS);
        float ry = 1.0f / sqrtf(var[c].y + EPS);
        float2 dn;
        dn.x = (dv[c].x - mean[c].x) * rx * g + bb;
        dn.y = (dv[c].y - mean[c].y) * ry * g + bb;
        g_D[(size_t)(bp * 4 + c) * NPOS + t] = dn;
    }
}

// ---------------------------------------------------------------------------
// Kernel B: per-signal stacks. grid=(128 bpair, 10 siggroups), block=128,
// 4 contiguous positions per thread.
// ---------------------------------------------------------------------------

extern "C" __global__ void __launch_bounds__(128)
sig_kernel(const float* __restrict__ sw1, const float* __restrict__ sb1,
           const float* __restrict__ sw2, const float* __restrict__ sb2,
           const float* __restrict__ sw3, const float* __restrict__ sb3,
           const float* __restrict__ sw4, const float* __restrict__ sb4,
           float* __restrict__ out) {
    extern __shared__ unsigned char sm[];
    float2* D  = (float2*)sm;         // 4 * CST
    float2* H1 = D + 4 * CST;         // 8 * CST
    float2* H2 = H1 + 8 * CST;        // 4 * CST
    float2* H3 = H1;                  // alias: 2 * CST (H1 dead when written)
    float*  W  = (float*)(H2 + 4 * CST);  // 449 floats

    const int tid  = threadIdx.x;
    const int bp   = blockIdx.x;
    const int base = tid * 4;

    // load d for this batch pair
    {
        const float2* gd = g_D + (size_t)bp * 4 * NPOS;
        for (int i = tid; i < 4 * NPOS; i += 128) {
            int c = i >> 9, p = i & 511;
            D[sidx(c, p)] = gd[i];
        }
    }
    __syncthreads();
    fill_halo(D, 4, tid);
    __syncthreads();

    const float* ws1 = W,       * wb1 = W + 224;
    const float* ws2 = W + 232, * wb2 = W + 392;
    const float* ws3 = W + 396, * wb3 = W + 436;
    const float* ws4 = W + 438, * wb4 = W + 448;

    for (int sl = 0; sl < 5; sl++) {
        const int sig = blockIdx.y * 5 + sl;
        __syncthreads();   // previous signal fully consumed W / H buffers

        // stage this signal's weights: w1(224) b1(8) w2(160) b2(4) w3(40) b3(2) w4(10) b4(1)
        for (int i = tid; i < 449; i += 128) {
            float v;
            if      (i < 224) v = sw1[sig * 224 + i];
            else if (i < 232) v = sb1[sig * 8   + (i - 224)];
            else if (i < 392) v = sw2[sig * 160 + (i - 232)];
            else if (i < 396) v = sb2[sig * 4   + (i - 392)];
            else if (i < 436) v = sw3[sig * 40  + (i - 396)];
            else if (i < 438) v = sb3[sig * 2   + (i - 436)];
            else if (i < 448) v = sw4[sig * 10  + (i - 438)];
            else              v = sb4[sig];
            W[i] = v;
        }
        __syncthreads();

        // ---- Layer 1: 4 -> 8, k7, d1, pad3 (no act) ----
        #pragma unroll
        for (int og = 0; og < 8; og += 4) {
            float2 acc[4][4];
            #pragma unroll
            for (int oo = 0; oo < 4; oo++) {
                float b = wb1[og + oo];
                #pragma unroll
                for (int r = 0; r < 4; r++) acc[oo][r] = make_float2(b, b);
            }
            #pragma unroll
            for (int c = 0; c < 4; c++) {
                float2 in[10];
                #pragma unroll
                for (int i = 0; i < 10; i++) in[i] = D[sidx(c, base - 3 + i)];
                #pragma unroll
                for (int oo = 0; oo < 4; oo++)
                    #pragma unroll
                    for (int j = 0; j < 7; j++) {
                        float w = ws1[(og + oo) * 28 + c * 7 + j];
                        float2 wv = make_float2(w, w);
                        #pragma unroll
                        for (int r = 0; r < 4; r++)
                            acc[oo][r] = ffma2(wv, in[r + j], acc[oo][r]);
                    }
            }
            #pragma unroll
            for (int oo = 0; oo < 4; oo++)
                #pragma unroll
                for (int r = 0; r < 4; r++)
                    H1[sidx(og + oo, base + r)] = acc[oo][r];
        }
        __syncthreads(); fill_halo(H1, 8, tid); __syncthreads();

        // ---- Layer 2: 8 -> 4, k5, d1, pad2, SELU ----
        {
            float2 acc[4][4];
            #pragma unroll
            for (int o = 0; o < 4; o++) {
                float b = wb2[o];
                #pragma unroll
                for (int r = 0; r < 4; r++) acc[o][r] = make_float2(b, b);
            }
            #pragma unroll
            for (int c = 0; c < 8; c++) {
                float2 in[8];
                #pragma unroll
                for (int i = 0; i < 8; i++) in[i] = H1[sidx(c, base - 2 + i)];
                #pragma unroll
                for (int o = 0; o < 4; o++)
                    #pragma unroll
                    for (int j = 0; j < 5; j++) {
                        float w = ws2[o * 40 + c * 5 + j];
                        float2 wv = make_float2(w, w);
                        #pragma unroll
                        for (int r = 0; r < 4; r++)
                            acc[o][r] = ffma2(wv, in[r + j], acc[o][r]);
                    }
            }
            __syncthreads();   // keep H1-read / later H3-write (alias) ordering simple
            #pragma unroll
            for (int o = 0; o < 4; o++)
                #pragma unroll
                for (int r = 0; r < 4; r++)
                    H2[sidx(o, base + r)] = selu2(acc[o][r]);
        }
        __syncthreads(); fill_halo(H2, 4, tid); __syncthreads();

        // ---- Layer 3: 4 -> 2, k5, d1, pad2 (no act). Writes H3 (aliases H1) ----
        {
            float2 acc[2][4];
            #pragma unroll
            for (int o = 0; o < 2; o++) {
                float b = wb3[o];
                #pragma unroll
                for (int r = 0; r < 4; r++) acc[o][r] = make_float2(b, b);
            }
            #pragma unroll
            for (int c = 0; c < 4; c++) {
                float2 in[8];
                #pragma unroll
                for (int i = 0; i < 8; i++) in[i] = H2[sidx(c, base - 2 + i)];
                #pragma unroll
                for (int o = 0; o < 2; o++)
                    #pragma unroll
                    for (int j = 0; j < 5; j++) {
                        float w = ws3[o * 20 + c * 5 + j];
                        float2 wv = make_float2(w, w);
                        #pragma unroll
                        for (int r = 0; r < 4; r++)
                            acc[o][r] = ffma2(wv, in[r + j], acc[o][r]);
                    }
            }
            #pragma unroll
            for (int o = 0; o < 2; o++)
                #pragma unroll
                for (int r = 0; r < 4; r++)
                    H3[sidx(o, base + r)] = acc[o][r];
        }
        __syncthreads(); fill_halo(H3, 2, tid); __syncthreads();

        // ---- Layer 4: 2 -> 1, k5, d2, pad4, SELU -> global ----
        {
            float b = wb4[0];
            float2 acc[4];
            #pragma unroll
            for (int r = 0; r < 4; r++) acc[r] = make_float2(b, b);
            #pragma unroll
            for (int c = 0; c < 2; c++) {
                float2 in[12];
                #pragma unroll
                for (int i = 0; i < 12; i++) in[i] = H3[sidx(c, base - 4 + i)];
                #pragma unroll
                for (int j = 0; j < 5; j++) {
                    float w = ws4[c * 5 + j];
                    float2 wv = make_float2(w, w);
                    #pragma unroll
                    for (int r = 0; r < 4; r++)
                        acc[r] = ffma2(wv, in[r + 2 * j], acc[r]);
                }
            }
            const size_t o0 = ((size_t)(2 * bp)     * 50 + sig) * NPOS + base;
            const size_t o1 = ((size_t)(2 * bp + 1) * 50 + sig) * NPOS + base;
            #pragma unroll
            for (int r = 0; r < 4; r++) {
                float2 v = selu2(acc[r]);
                out[o0 + r] = v.x;
                out[o1 + r] = v.y;
            }
        }
    }
}

// ---------------------------------------------------------------------------
// launch
// ---------------------------------------------------------------------------

static const int SMEM_PREP = (16 * CST) * (int)sizeof(float2) + 336 * 4 + 64 * (int)sizeof(float2);
static const int SMEM_SIG  = (16 * CST) * (int)sizeof(float2) + 452 * 4;

extern "C" void kernel_launch(void* const* d_in, const int* in_sizes, int n_in,
                              void* d_out, int out_size) {
    const float* lat = (const float*)d_in[0];
    const float* shw1 = (const float*)d_in[1];
    const float* shb1 = (const float*)d_in[2];
    const float* shw2 = (const float*)d_in[3];
    const float* shb2 = (const float*)d_in[4];
    const float* lng  = (const float*)d_in[5];
    const float* lnb  = (const float*)d_in[6];
    const float* sgw1 = (const float*)d_in[7];
    const float* sgb1 = (const float*)d_in[8];
    const float* sgw2 = (const float*)d_in[9];
    const float* sgb2 = (const float*)d_in[10];
    const float* sgw3 = (const float*)d_in[11];
    const float* sgb3 = (const float*)d_in[12];
    const float* sgw4 = (const float*)d_in[13];
    const float* sgb4 = (const float*)d_in[14];
    float* out = (float*)d_out;

    cudaFuncSetAttribute(prep_kernel, cudaFuncAttributeMaxDynamicSharedMemorySize, SMEM_PREP);
    cudaFuncSetAttribute(sig_kernel,  cudaFuncAttributeMaxDynamicSharedMemorySize, SMEM_SIG);

    prep_kernel<<<NBP, 512, SMEM_PREP>>>(lat, shw1, shb1, shw2, shb2, lng, lnb);
    sig_kernel<<<dim3(NBP, 10), 128, SMEM_SIG>>>(sgw1, sgb1, sgw2, sgb2,
                                                 sgw3, sgb3, sgw4, sgb4, out);
}